// round 1
// baseline (speedup 1.0000x reference)
#include <cuda_runtime.h>
#include <cuda_bf16.h>
#include <math.h>

// Problem constants (GaussionConvolution_F): N=100000, F=256, UNITS=256, DIM=128
#define F_DIM   256
#define UNITS   256
#define DIM     128
#define N_MAX   100000
#define RPB     16      // rows per block in GEMM

// Scratch: packed per-node row [ mean*att (128) | var*att^2 (128) ]
__device__ float g_x[(size_t)N_MAX * UNITS];     // ~102.4 MB
__device__ int   g_rowptr[N_MAX + 1];
__device__ float g_kl;

// ---------------------------------------------------------------------------
// Kernel 1: build CSR row_ptr from sorted row[] via binary search; zero g_kl.
// ---------------------------------------------------------------------------
__global__ void build_rowptr_kernel(const int* __restrict__ row, int n, int e) {
    int i = blockIdx.x * blockDim.x + threadIdx.x;
    if (i == 0) g_kl = 0.0f;
    if (i > n) return;
    // lower_bound: first idx with row[idx] >= i
    int lo = 0, hi = e;
    while (lo < hi) {
        int mid = (lo + hi) >> 1;
        if (row[mid] < i) lo = mid + 1; else hi = mid;
    }
    g_rowptr[i] = lo;
}

// ---------------------------------------------------------------------------
// Kernel 2: fused GEMM + activations + KL + scatter-prep.
// Block = 128 threads (one per dim d in [0,128)), each computes cols d and
// d+128 of h for RPB rows, then:
//   mean = elu(h[:, d]),  var = relu(h[:, d+128]),  att = exp(-var)
//   g_x[n, d]      = mean * att
//   g_x[n, d+128]  = var  * att * att
//   kl += 0.5/DIM * (mean^2 + var - log(1e-8+var) - 1)
// ---------------------------------------------------------------------------
__global__ __launch_bounds__(DIM) void gemm_act_kernel(
    const float* __restrict__ feat,   // [n, F]
    const float* __restrict__ W,      // [F, UNITS]
    int n)
{
    __shared__ float fs[RPB][F_DIM];
    __shared__ float kl_red[4];

    const int row0 = blockIdx.x * RPB;
    const int t = threadIdx.x;                 // dim index d, 0..127
    const int nrows = min(RPB, n - row0);

    // Cooperative load of RPB feature rows (float4, coalesced)
    {
        const float4* src = reinterpret_cast<const float4*>(feat + (size_t)row0 * F_DIM);
        float4* dst = reinterpret_cast<float4*>(&fs[0][0]);
        const int total4 = nrows * (F_DIM / 4);
        for (int i = t; i < total4; i += DIM) dst[i] = src[i];
    }
    __syncthreads();

    float accm[RPB], accv[RPB];
#pragma unroll
    for (int r = 0; r < RPB; r++) { accm[r] = 0.f; accv[r] = 0.f; }

#pragma unroll 4
    for (int k = 0; k < F_DIM; k++) {
        const float km = W[k * UNITS + t];          // col d
        const float kv = W[k * UNITS + DIM + t];    // col d+128
#pragma unroll
        for (int r = 0; r < RPB; r++) {
            const float f = fs[r][k];
            accm[r] = fmaf(f, km, accm[r]);
            accv[r] = fmaf(f, kv, accv[r]);
        }
    }

    // Epilogue
    float kl = 0.f;
#pragma unroll
    for (int r = 0; r < RPB; r++) {
        if (r >= nrows) break;
        const float hm = accm[r];
        const float hv = accv[r];
        const float m  = hm > 0.f ? hm : expm1f(hm);   // elu
        const float v  = hv > 0.f ? hv : 0.f;          // relu
        const float att = __expf(-v);
        kl += m * m + v - logf(1e-8f + v) - 1.f;
        const size_t base = (size_t)(row0 + r) * UNITS;
        g_x[base + t]       = m * att;
        g_x[base + DIM + t] = v * att * att;
    }
    kl *= 0.5f / (float)DIM;

    // Block reduction of kl (4 warps)
#pragma unroll
    for (int off = 16; off > 0; off >>= 1)
        kl += __shfl_down_sync(0xFFFFFFFFu, kl, off);
    const int lane = t & 31, wid = t >> 5;
    if (lane == 0) kl_red[wid] = kl;
    __syncthreads();
    if (t == 0) {
        float s = kl_red[0] + kl_red[1] + kl_red[2] + kl_red[3];
        atomicAdd(&g_kl, s);
    }
}

// ---------------------------------------------------------------------------
// Kernel 3: fused dual SpMM. One warp per output node.
// out[n, 0:128]   = sum_e adj1[e] * g_x[col[e], 0:128]
// out[n, 128:256] = sum_e adj2[e] * g_x[col[e], 128:256]
// Also writes kl scalar to out[n*UNITS] slot (global thread 0).
// ---------------------------------------------------------------------------
__global__ void spmm_kernel(
    const int* __restrict__ col,
    const float* __restrict__ a1,
    const float* __restrict__ a2,
    float* __restrict__ out,
    int n, int write_kl)
{
    const int gtid = blockIdx.x * blockDim.x + threadIdx.x;
    if (gtid == 0 && write_kl) {
        out[(size_t)n * UNITS] = g_kl;
    }
    const int node = gtid >> 5;
    const int lane = threadIdx.x & 31;
    if (node >= n) return;

    const int s = g_rowptr[node];
    const int e = g_rowptr[node + 1];

    float4 am = make_float4(0.f, 0.f, 0.f, 0.f);
    float4 av = make_float4(0.f, 0.f, 0.f, 0.f);

    for (int i = s; i < e; i++) {
        const int c = __ldg(&col[i]);
        const float v1 = __ldg(&a1[i]);
        const float v2 = __ldg(&a2[i]);
        const float4* xr = reinterpret_cast<const float4*>(g_x + (size_t)c * UNITS);
        const float4 xm = __ldg(&xr[lane]);
        const float4 xv = __ldg(&xr[32 + lane]);
        am.x = fmaf(v1, xm.x, am.x);
        am.y = fmaf(v1, xm.y, am.y);
        am.z = fmaf(v1, xm.z, am.z);
        am.w = fmaf(v1, xm.w, am.w);
        av.x = fmaf(v2, xv.x, av.x);
        av.y = fmaf(v2, xv.y, av.y);
        av.z = fmaf(v2, xv.z, av.z);
        av.w = fmaf(v2, xv.w, av.w);
    }

    float4* o = reinterpret_cast<float4*>(out + (size_t)node * UNITS);
    o[lane] = am;
    o[32 + lane] = av;
}

// ---------------------------------------------------------------------------
extern "C" void kernel_launch(void* const* d_in, const int* in_sizes, int n_in,
                              void* d_out, int out_size) {
    const float* feat = (const float*)d_in[0];   // [N, F]
    const float* W    = (const float*)d_in[1];   // [F, UNITS]
    const int*   row  = (const int*)d_in[2];     // [E] sorted
    const int*   col  = (const int*)d_in[3];     // [E]
    const float* a1   = (const float*)d_in[4];   // [E]
    const float* a2   = (const float*)d_in[5];   // [E]
    float* out = (float*)d_out;

    const int n = in_sizes[0] / F_DIM;
    const int e = in_sizes[2];
    const int write_kl = (out_size > n * UNITS) ? 1 : 0;

    // 1) CSR row pointers + zero kl accumulator
    {
        const int threads = 256;
        const int blocks = (n + 1 + threads - 1) / threads;
        build_rowptr_kernel<<<blocks, threads>>>(row, n, e);
    }

    // 2) GEMM + activations + KL
    {
        const int blocks = (n + RPB - 1) / RPB;
        gemm_act_kernel<<<blocks, DIM>>>(feat, W, n);
    }

    // 3) Dual SpMM (+ kl scalar write)
    {
        const int threads = 256;                 // 8 warps = 8 nodes per block
        const int warps_needed = n;
        const int blocks = (warps_needed + (threads / 32) - 1) / (threads / 32);
        spmm_kernel<<<blocks, threads>>>(col, a1, a2, out, n, write_kl);
    }
}

// round 2
// speedup vs baseline: 1.4178x; 1.4178x over previous
#include <cuda_runtime.h>
#include <cuda_bf16.h>
#include <math.h>

// Problem constants: N=100000, F=256, UNITS=256, DIM=128
#define F_DIM   256
#define UNITS   256
#define DIM     128
#define N_MAX   100000
#define RPB     32            // rows per block in GEMM
#define RH      (RPB / 2)     // row pairs

// Scratch: packed per-node row [ mean*att (128) | var*att^2 (128) ]
__device__ float g_x[(size_t)N_MAX * UNITS];     // ~102.4 MB
__device__ int   g_rowptr[N_MAX + 1];
__device__ float g_kl;

// f32x2 packed helpers (Blackwell packed fp32 pipe; 2 FMAs / instr)
__device__ __forceinline__ unsigned long long pack_dup(float a) {
    unsigned long long r;
    asm("mov.b64 %0, {%1, %1};" : "=l"(r) : "r"(__float_as_uint(a)));
    return r;
}
__device__ __forceinline__ unsigned long long fma2(unsigned long long a,
                                                   unsigned long long b,
                                                   unsigned long long c) {
    unsigned long long d;
    asm("fma.rn.f32x2 %0, %1, %2, %3;" : "=l"(d) : "l"(a), "l"(b), "l"(c));
    return d;
}
__device__ __forceinline__ void unpack2(unsigned long long v, float& lo, float& hi) {
    unsigned int a, b;
    asm("mov.b64 {%0, %1}, %2;" : "=r"(a), "=r"(b) : "l"(v));
    lo = __uint_as_float(a);
    hi = __uint_as_float(b);
}

// ---------------------------------------------------------------------------
// Kernel 1: CSR row_ptr via boundary scatter (row[] is sorted). O(E) total.
// Thread i covers boundary between row[i-1] and row[i]; thread E covers tail.
// ---------------------------------------------------------------------------
__global__ void build_rowptr_kernel(const int* __restrict__ row, int n, int e) {
    int i = blockIdx.x * blockDim.x + threadIdx.x;
    if (i == 0) g_kl = 0.0f;
    if (i > e) return;
    int prev = (i == 0) ? -1 : row[i - 1];
    int cur  = (i == e) ? n  : row[i];
    for (int j = prev + 1; j <= cur; j++) g_rowptr[j] = i;
}

// ---------------------------------------------------------------------------
// Kernel 2: fused GEMM + activations + KL + scatter-prep, packed f32x2 math.
// Block = 128 threads; thread t owns output columns t and t+128 for RPB rows.
// Features staged transposed in smem so row-pairs are b64-contiguous.
// ---------------------------------------------------------------------------
__global__ __launch_bounds__(DIM) void gemm_act_kernel(
    const float* __restrict__ feat,   // [n, F]
    const float* __restrict__ W,      // [F, UNITS]
    int n)
{
    // +2 pad: keeps 8B alignment of each k-row and spreads STS banks
    __shared__ float fs[F_DIM][RPB + 2];
    __shared__ float kl_red[4];

    const int row0 = blockIdx.x * RPB;
    const int t = threadIdx.x;
    const int nrows = min(RPB, n - row0);

    // Cooperative transpose-load of RPB feature rows (float4 gmem, coalesced)
    {
        const float4* src = reinterpret_cast<const float4*>(feat + (size_t)row0 * F_DIM);
        const int total4 = nrows * (F_DIM / 4);
        for (int i = t; i < total4; i += DIM) {
            const float4 v = src[i];
            const int r  = i >> 6;            // i / 64
            const int k4 = (i & 63) << 2;     // (i % 64) * 4
            fs[k4 + 0][r] = v.x;
            fs[k4 + 1][r] = v.y;
            fs[k4 + 2][r] = v.z;
            fs[k4 + 3][r] = v.w;
        }
    }
    __syncthreads();

    unsigned long long accm[RH], accv[RH];
#pragma unroll
    for (int p = 0; p < RH; p++) { accm[p] = 0ull; accv[p] = 0ull; }

#pragma unroll 2
    for (int k = 0; k < F_DIM; k++) {
        const unsigned long long wm2 = pack_dup(__ldg(&W[k * UNITS + t]));
        const unsigned long long wv2 = pack_dup(__ldg(&W[k * UNITS + DIM + t]));
        const unsigned long long* fr =
            reinterpret_cast<const unsigned long long*>(&fs[k][0]);
#pragma unroll
        for (int p = 0; p < RH; p++) {
            const unsigned long long f2 = fr[p];   // rows (2p, 2p+1), broadcast LDS
            accm[p] = fma2(f2, wm2, accm[p]);
            accv[p] = fma2(f2, wv2, accv[p]);
        }
    }

    // Epilogue: activations, attention, KL, scratch writes
    float kl = 0.f;
#pragma unroll
    for (int p = 0; p < RH; p++) {
        float hm0, hm1, hv0, hv1;
        unpack2(accm[p], hm0, hm1);
        unpack2(accv[p], hv0, hv1);
#pragma unroll
        for (int q = 0; q < 2; q++) {
            const int r = 2 * p + q;
            if (r >= nrows) break;
            const float hm = q ? hm1 : hm0;
            const float hv = q ? hv1 : hv0;
            const float m  = hm > 0.f ? hm : expm1f(hm);   // elu
            const float v  = hv > 0.f ? hv : 0.f;          // relu
            const float att = __expf(-v);
            kl += m * m + v - logf(1e-8f + v) - 1.f;
            const size_t base = (size_t)(row0 + r) * UNITS;
            g_x[base + t]       = m * att;
            g_x[base + DIM + t] = v * att * att;
        }
    }
    kl *= 0.5f / (float)DIM;

#pragma unroll
    for (int off = 16; off > 0; off >>= 1)
        kl += __shfl_down_sync(0xFFFFFFFFu, kl, off);
    const int lane = t & 31, wid = t >> 5;
    if (lane == 0) kl_red[wid] = kl;
    __syncthreads();
    if (t == 0) {
        atomicAdd(&g_kl, kl_red[0] + kl_red[1] + kl_red[2] + kl_red[3]);
    }
}

// ---------------------------------------------------------------------------
// Kernel 3: fused dual SpMM. TWO warps per node (half = mean / var side).
// out[n, h*128 : h*128+128] = sum_e adj_h[e] * g_x[col[e], h*128 : ...]
// ---------------------------------------------------------------------------
__global__ void spmm_kernel(
    const int* __restrict__ col,
    const float* __restrict__ a1,
    const float* __restrict__ a2,
    float* __restrict__ out,
    int n, int write_kl)
{
    const int gtid = blockIdx.x * blockDim.x + threadIdx.x;
    if (gtid == 0 && write_kl) out[(size_t)n * UNITS] = g_kl;

    const int work = gtid >> 5;
    const int node = work >> 1;
    const int half = work & 1;
    const int lane = threadIdx.x & 31;
    if (node >= n) return;

    const int s = g_rowptr[node];
    const int e = g_rowptr[node + 1];
    const float* __restrict__ av = half ? a2 : a1;

    float4 acc = make_float4(0.f, 0.f, 0.f, 0.f);

    int i = s;
    // unroll-by-2 for memory-level parallelism
    for (; i + 1 < e; i += 2) {
        const int c0 = __ldg(&col[i]);
        const int c1 = __ldg(&col[i + 1]);
        const float w0 = __ldg(&av[i]);
        const float w1 = __ldg(&av[i + 1]);
        const float4 x0 = __ldg(&reinterpret_cast<const float4*>(
            g_x + (size_t)c0 * UNITS + half * DIM)[lane]);
        const float4 x1 = __ldg(&reinterpret_cast<const float4*>(
            g_x + (size_t)c1 * UNITS + half * DIM)[lane]);
        acc.x = fmaf(w0, x0.x, acc.x); acc.y = fmaf(w0, x0.y, acc.y);
        acc.z = fmaf(w0, x0.z, acc.z); acc.w = fmaf(w0, x0.w, acc.w);
        acc.x = fmaf(w1, x1.x, acc.x); acc.y = fmaf(w1, x1.y, acc.y);
        acc.z = fmaf(w1, x1.z, acc.z); acc.w = fmaf(w1, x1.w, acc.w);
    }
    if (i < e) {
        const int c0 = __ldg(&col[i]);
        const float w0 = __ldg(&av[i]);
        const float4 x0 = __ldg(&reinterpret_cast<const float4*>(
            g_x + (size_t)c0 * UNITS + half * DIM)[lane]);
        acc.x = fmaf(w0, x0.x, acc.x); acc.y = fmaf(w0, x0.y, acc.y);
        acc.z = fmaf(w0, x0.z, acc.z); acc.w = fmaf(w0, x0.w, acc.w);
    }

    reinterpret_cast<float4*>(out + (size_t)node * UNITS + half * DIM)[lane] = acc;
}

// ---------------------------------------------------------------------------
extern "C" void kernel_launch(void* const* d_in, const int* in_sizes, int n_in,
                              void* d_out, int out_size) {
    const float* feat = (const float*)d_in[0];
    const float* W    = (const float*)d_in[1];
    const int*   row  = (const int*)d_in[2];
    const int*   col  = (const int*)d_in[3];
    const float* a1   = (const float*)d_in[4];
    const float* a2   = (const float*)d_in[5];
    float* out = (float*)d_out;

    const int n = in_sizes[0] / F_DIM;
    const int e = in_sizes[2];
    const int write_kl = (out_size > n * UNITS) ? 1 : 0;

    {   // 1) CSR row pointers via scatter
        const int threads = 256;
        const int blocks = (e + 1 + threads - 1) / threads;
        build_rowptr_kernel<<<blocks, threads>>>(row, n, e);
    }
    {   // 2) GEMM (f32x2 packed) + activations + KL
        const int blocks = (n + RPB - 1) / RPB;
        gemm_act_kernel<<<blocks, DIM>>>(feat, W, n);
    }
    {   // 3) Dual SpMM, 2 warps per node
        const int threads = 256;
        const int warps_needed = 2 * n;
        const int blocks = (warps_needed + (threads / 32) - 1) / (threads / 32);
        spmm_kernel<<<blocks, threads>>>(col, a1, a2, out, n, write_kl);
    }
}